// round 10
// baseline (speedup 1.0000x reference)
#include <cuda_runtime.h>

#define NB     256
#define NPIX   (1024*1024)
#define NBATCH 16
#define G      4                  // images per group (50 MB — L2-safe window)
#define NGROUP (NBATCH / G)
#define IT     2                  // float4 items per thread
#define TPB    256
#define BLKX   (NPIX / 4 / (TPB * IT))   // 512 blocks per image
#define NSUB   8                  // one sub-histogram per warp

// Scratch (no allocations). g_histo is zero at load and re-zeroed by
// lut_kernel after consumption, so every graph replay sees zeros.
__device__ int   g_histo[NBATCH][NB];
__device__ float g_lut[NBATCH][NB];
__device__ float g_step[NBATCH];

__device__ __forceinline__ float clip01(float x) {
    return fminf(fmaxf(x, 0.0f), 1.0f);
}

// ---------------- hist body: per-warp sub-histograms (best measured) -------
__device__ __forceinline__ void hist_body(const float* __restrict__ img,
                                          int b, int bx, int* sub) {
    for (int i = threadIdx.x; i < NSUB * NB; i += TPB) sub[i] = 0;
    __syncthreads();

    const size_t base = (size_t)b * 3 * NPIX;
    const float4* __restrict__ R  = (const float4*)(img + base);
    const float4* __restrict__ Gc = (const float4*)(img + base + NPIX);
    const float4* __restrict__ B  = (const float4*)(img + base + 2 * NPIX);

    const int tile = bx * (TPB * IT);
    const float scale = (float)(256.0 / 255.0);   // NUM_BINS / 255.0 in f32
    int* mysub = &sub[(threadIdx.x >> 5) * NB];

    #pragma unroll
    for (int k = 0; k < IT; k++) {
        int i = tile + k * TPB + threadIdx.x;
        float4 r4 = R[i], g4 = Gc[i], b4 = B[i];
        #pragma unroll
        for (int c = 0; c < 4; c++) {
            float r  = clip01(((const float*)&r4)[c]);
            float g  = clip01(((const float*)&g4)[c]);
            float bb = clip01(((const float*)&b4)[c]);
            float y = 0.299f * r + 0.587f * g + 0.114f * bb;
            int bin = (int)floorf(y * 255.0f * scale);
            bin = min(max(bin, 0), NB - 1);
            atomicAdd(&mysub[bin], 1);
        }
    }
    __syncthreads();

    int t = threadIdx.x;           // TPB == NB
    int tot = 0;
    #pragma unroll
    for (int w = 0; w < NSUB; w++) tot += sub[w * NB + t];
    if (tot) atomicAdd(&g_histo[b][t], tot);
}

// ---------------- map body --------------------------------------------------
__device__ __forceinline__ void map_body(const float* __restrict__ img,
                                         float* __restrict__ out,
                                         int b, int bx, float* lut) {
    __shared__ float stepv;
    for (int i = threadIdx.x; i < NB; i += TPB) lut[i] = g_lut[b][i];
    if (threadIdx.x == 0) stepv = g_step[b];
    __syncthreads();

    const bool identity = (stepv == 0.0f);

    const size_t base = (size_t)b * 3 * NPIX;
    const float4* __restrict__ R  = (const float4*)(img + base);
    const float4* __restrict__ Gc = (const float4*)(img + base + NPIX);
    const float4* __restrict__ B  = (const float4*)(img + base + 2 * NPIX);
    float4* __restrict__ Ro = (float4*)(out + base);
    float4* __restrict__ Go = (float4*)(out + base + NPIX);
    float4* __restrict__ Bo = (float4*)(out + base + 2 * NPIX);

    const int tile = bx * (TPB * IT);
    const float inv255 = 1.0f / 255.0f;

    #pragma unroll
    for (int k = 0; k < IT; k++) {
        int i = tile + k * TPB + threadIdx.x;
        float4 r4 = __ldcs(R + i);     // demote after last touch
        float4 g4 = __ldcs(Gc + i);
        float4 b4 = __ldcs(B + i);
        float4 ro, go, bo;
        #pragma unroll
        for (int c = 0; c < 4; c++) {
            float r  = clip01(((const float*)&r4)[c]);
            float g  = clip01(((const float*)&g4)[c]);
            float bb = clip01(((const float*)&b4)[c]);

            float y = 0.299f * r + 0.587f * g + 0.114f * bb;
            float u = -0.147f * r - 0.289f * g + 0.436f * bb;
            float v = 0.615f * r - 0.515f * g - 0.100f * bb;

            float t = y * 255.0f;
            int gi = min(max((int)t, 0), NB - 1);
            float outv = identity ? t : lut[gi];
            float ye = outv * inv255;

            ((float*)&ro)[c] = ye + 1.14f * v;
            ((float*)&go)[c] = ye - 0.396f * u - 0.581f * v;
            ((float*)&bo)[c] = ye + 2.029f * u;
        }
        __stcs(Ro + i, ro);            // evict-first: never displaces staging
        __stcs(Go + i, go);
        __stcs(Bo + i, bo);
    }
}

// ---------------- kernels ---------------------------------------------------
__global__ void hist_kernel(const float* __restrict__ img, int img_base) {
    __shared__ int sub[NSUB * NB];
    hist_body(img, img_base + blockIdx.y, blockIdx.x, sub);
}

__global__ void map_kernel(const float* __restrict__ img, float* __restrict__ out,
                           int img_base) {
    __shared__ float lut[NB];
    map_body(img, out, img_base + blockIdx.y, blockIdx.x, lut);
}

// Merged-role kernel: even blockIdx.y rows hist group `hist_base`, odd rows
// map group `map_base`. Interleaved roles guarantee block-level mixing of
// ATOMS-bound (hist) and DRAM-bound (map) work in every wave.
__global__ void fused_kernel(const float* __restrict__ img,
                             float* __restrict__ out,
                             int map_base, int hist_base) {
    __shared__ int sub[NSUB * NB];     // 8 KB; aliased as lut floats for map
    const int sel = blockIdx.y;
    if (sel & 1) {
        map_body(img, out, map_base + (sel >> 1), blockIdx.x, (float*)sub);
    } else {
        hist_body(img, hist_base + (sel >> 1), blockIdx.x, sub);
    }
}

// LUT: one block per image; resets the histogram for the next graph replay.
__global__ void lut_kernel(int img_base) {
    const int b = img_base + blockIdx.x;
    const int t = threadIdx.x;

    __shared__ float h[NB];
    __shared__ float s[NB];
    __shared__ int   lastIdx;

    float hv = (float)g_histo[b][t];
    g_histo[b][t] = 0;                    // reset for next replay
    h[t] = hv;
    s[t] = hv;
    if (t == 0) lastIdx = 0;
    __syncthreads();

    for (int off = 1; off < NB; off <<= 1) {
        float add = (t >= off) ? s[t - off] : 0.0f;
        __syncthreads();
        s[t] += add;
        __syncthreads();
    }

    if (hv > 0.0f) atomicMax(&lastIdx, t);
    __syncthreads();

    float total    = s[NB - 1];
    float last_val = h[lastIdx];
    float step     = floorf(__fdiv_rn(total - last_val, 255.0f));
    float safe     = fmaxf(step, 1.0f);
    float half     = floorf(__fdiv_rn(step, 2.0f));

    float lv;
    if (t == 0) {
        lv = 0.0f;
    } else {
        lv = floorf(__fdiv_rn(s[t - 1] + half, safe));
        lv = fminf(fmaxf(lv, 0.0f), 255.0f);
    }
    g_lut[b][t] = lv;
    if (t == 0) g_step[b] = step;
}

extern "C" void kernel_launch(void* const* d_in, const int* in_sizes, int n_in,
                              void* d_out, int out_size) {
    const float* img = (const float*)d_in[0];
    float*       out = (float*)d_out;

    // Software pipeline on ONE stream; concurrency comes from merged grids:
    // hist(0) | lut | [map0+hist1] | lut | [map1+hist2] | lut | [map2+hist3]
    //         | lut | map(3)
    {
        dim3 grid(BLKX, G);
        hist_kernel<<<grid, TPB>>>(img, 0);
        lut_kernel<<<G, NB>>>(0);
    }
    for (int g = 1; g < NGROUP; g++) {
        dim3 grid(BLKX, 2 * G);
        fused_kernel<<<grid, TPB>>>(img, out, (g - 1) * G, g * G);
        lut_kernel<<<G, NB>>>(g * G);
    }
    {
        dim3 grid(BLKX, G);
        map_kernel<<<grid, TPB>>>(img, out, (NGROUP - 1) * G);
    }
}